// round 15
// baseline (speedup 1.0000x reference)
#include <cuda_runtime.h>
#include <cstdint>

// Problem constants
#define B_DIM   16
#define L_DIM   160000
#define N_WT    10
#define WT_LEN  512
#define FIR_TAPS 31
#define WT_TOT  (N_WT * WT_LEN)

// Blocked-scan parameters (XLA ReduceWindowRewriter, base_length = 16)
#define NS1 10000
#define NS2 625
#define NS3 40
#define NS4 3

// k_main tiling: 640 threads x 5 samples = 3200-sample tiles, 50 tiles/row
#define TPB   640
#define SAMP  5
#define TILE  (TPB * SAMP)          // 3200
#define NGRP  (TILE / 16)           // 200 16-groups per tile

// k_s1 tiling: 20 tiles/row, 500 S1 groups per tile (512-thread blocks)
#define S1_TILES 20
#define S1_GRP   500

// k_main dynamic smem: transposed pair table + finished cumsums + S1/O2 stage
#define SP_BYTES   (WT_LEN * 5 * 16)   // 40960 (512 x 5 float4)
#define SO0_BYTES  (TILE * 4)          // 12800
#define SS1_BYTES  (224 * 4)           // 896  (<=216 used)
#define SO2_BYTES  (16 * 4)            // 64
#define SMEM_MAIN  (SP_BYTES + SO0_BYTES + SS1_BYTES + SO2_BYTES)

__device__ __forceinline__ float KF() { return (float)(512.0 / 16000.0); }

// Scratch
__device__ float  g_S1[B_DIM][NS1];     // 16-block sums of increments
__device__ float  g_O2[B_DIM][NS2];     // composed inclusive scan at level 2
__device__ float4 g_wtp4t[WT_LEN * 5];  // transposed pairs [i][j]={lo2j,hi2j,lo2j+1,hi2j+1}

// ---------------------------------------------------------------------------
// k_s1: pure S1 — one 16-group per thread, 4x LDG.128, strict sequential rn
// adds in register order (verified bracketing).  launch_bounds(512,3) caps
// regs to lift residency to 3 blocks/SM.
// ---------------------------------------------------------------------------
__global__ void __launch_bounds__(512, 3) k_s1(const float* __restrict__ pitch)
{
    const int tid = threadIdx.x;
    const int j = blockIdx.x * S1_GRP + tid;
    if (tid >= S1_GRP) return;
    const int b = blockIdx.y;
    const float k = KF();
    const float4* P4 = (const float4*)(pitch + b * L_DIM + (j << 4));
    float4 v0 = P4[0], v1 = P4[1], v2 = P4[2], v3 = P4[3];

    float acc = 0.0f;
    acc = __fadd_rn(acc, __fmul_rn(k, v0.x));
    acc = __fadd_rn(acc, __fmul_rn(k, v0.y));
    acc = __fadd_rn(acc, __fmul_rn(k, v0.z));
    acc = __fadd_rn(acc, __fmul_rn(k, v0.w));
    acc = __fadd_rn(acc, __fmul_rn(k, v1.x));
    acc = __fadd_rn(acc, __fmul_rn(k, v1.y));
    acc = __fadd_rn(acc, __fmul_rn(k, v1.z));
    acc = __fadd_rn(acc, __fmul_rn(k, v1.w));
    acc = __fadd_rn(acc, __fmul_rn(k, v2.x));
    acc = __fadd_rn(acc, __fmul_rn(k, v2.y));
    acc = __fadd_rn(acc, __fmul_rn(k, v2.z));
    acc = __fadd_rn(acc, __fmul_rn(k, v2.w));
    acc = __fadd_rn(acc, __fmul_rn(k, v3.x));
    acc = __fadd_rn(acc, __fmul_rn(k, v3.y));
    acc = __fadd_rn(acc, __fmul_rn(k, v3.z));
    acc = __fadd_rn(acc, __fmul_rn(k, v3.w));
    g_S1[b][j] = acc;
}

// ---------------------------------------------------------------------------
// k_scan: blocks 0..15: per-row S2 -> S3 -> S4 -> O4 -> O3 -> O2 (verified
// chain), writes g_O2 directly.  Blocks 16..20: FIR rows (2jj, 2jj+1) +
// transposed pair writeout.  smem is a UNION of the two paths (<48 KB).
// ---------------------------------------------------------------------------
__global__ void k_scan(const float* __restrict__ wtab,
                       const float* __restrict__ firh)
{
    __shared__ union {
        struct {
            float s1p[NS2 * 17];            // 42500 B
            float sS2[NS2];                 // 2500 B
            float sS3[NS3];
            float sS4[NS4];
            float sO4[NS4];
            float sO3[NS3];
        } sc;                               // ~45.3 KB
        struct {
            float srow[2][WT_LEN];          // 4096 B
            float sout[2][WT_LEN];          // 4096 B
            float sh[FIR_TAPS];
        } fir;                              // ~8.3 KB
    } u;

    const int tid = threadIdx.x;

    if (blockIdx.x >= B_DIM) {                  // FIR pair block
        const int jj = blockIdx.x - B_DIM;      // 0..4 -> rows 2jj, 2jj+1
        if (tid < FIR_TAPS) u.fir.sh[tid] = firh[tid];
        if (tid < WT_LEN) {
            u.fir.srow[0][tid] = wtab[(2 * jj    ) * WT_LEN + tid];
            u.fir.srow[1][tid] = wtab[(2 * jj + 1) * WT_LEN + tid];
        }
        __syncthreads();
        if (tid < WT_LEN) {
            #pragma unroll
            for (int rr = 0; rr < 2; rr++) {
                float s = 0.0f;
                #pragma unroll
                for (int k = 0; k < FIR_TAPS; k++) {
                    int j = (tid + k - 15 + WT_LEN) & 511;
                    s = __fadd_rn(s, __fmul_rn(u.fir.srow[rr][j], u.fir.sh[k]));
                }
                u.fir.sout[rr][tid] = s;
            }
        }
        __syncthreads();
        if (tid < WT_LEN) {
            int ip1 = (tid + 1) & 511;
            float4 v;
            v.x = u.fir.sout[0][tid]; v.y = u.fir.sout[0][ip1];
            v.z = u.fir.sout[1][tid]; v.w = u.fir.sout[1][ip1];
            g_wtp4t[tid * 5 + jj] = v;
        }
        return;
    }

    const int b = blockIdx.x;

    for (int i = tid; i < NS1; i += 1024)
        u.sc.s1p[(i >> 4) * 17 + (i & 15)] = g_S1[b][i];
    __syncthreads();

    if (tid < NS2) {                         // S2: strict 16-sums
        const float* row = u.sc.s1p + tid * 17;
        float acc = 0.0f;
        #pragma unroll
        for (int e = 0; e < 16; e++)
            acc = __fadd_rn(acc, row[e]);
        u.sc.sS2[tid] = acc;
    }
    __syncthreads();

    if (tid < NS3) {                         // S3 (625 padded to 640)
        float acc = 0.0f;
        for (int e = 0; e < 16; e++) {
            int idx = (tid << 4) + e;
            if (idx < NS2) acc = __fadd_rn(acc, u.sc.sS2[idx]);
        }
        u.sc.sS3[tid] = acc;
    }
    __syncthreads();

    if (tid < NS4) {                         // S4 (40 padded to 48)
        float acc = 0.0f;
        for (int e = 0; e < 16; e++) {
            int idx = (tid << 4) + e;
            if (idx < NS3) acc = __fadd_rn(acc, u.sc.sS3[idx]);
        }
        u.sc.sS4[tid] = acc;
    }
    __syncthreads();

    if (tid == 0) {                          // O4 sequential
        float acc = 0.0f;
        for (int m = 0; m < NS4; m++) {
            acc = __fadd_rn(acc, u.sc.sS4[m]);
            u.sc.sO4[m] = acc;
        }
    }
    __syncthreads();

    if (tid < NS3) {                         // O3
        int blk = tid >> 4;
        float acc = 0.0f;
        for (int m = (blk << 4); m <= tid; m++)
            acc = __fadd_rn(acc, u.sc.sS3[m]);
        u.sc.sO3[tid] = blk ? __fadd_rn(acc, u.sc.sO4[blk - 1]) : acc;
    }
    __syncthreads();

    if (tid < NS2) {                         // O2 -> global
        int blk = tid >> 4;
        float acc = 0.0f;
        for (int m = (blk << 4); m <= tid; m++)
            acc = __fadd_rn(acc, u.sc.sS2[m]);
        g_O2[b][tid] = blk ? __fadd_rn(acc, u.sc.sO3[blk - 1]) : acc;
    }
}

// ---------------------------------------------------------------------------
// k_main: O0 preamble composes O1[gj-1] locally from staged S1+O2 (same add
// chain as the old k_scan O1 pass — bitwise identical), then produces all
// 3200 finished cumsums.  Main loop identical to R13 (verified 43.5us).
// ---------------------------------------------------------------------------
__global__ void __launch_bounds__(TPB, 3) k_main(
        const float* __restrict__ pitch,
        const float* __restrict__ env,
        const float* __restrict__ att,
        float* __restrict__ out)
{
    extern __shared__ char smem_raw[];
    float4* sp4t = (float4*)smem_raw;                               // [512*5]
    float*  so0  = (float*)(smem_raw + SP_BYTES);                   // [3200]
    float*  sS1  = (float*)(smem_raw + SP_BYTES + SO0_BYTES);       // [224]
    float*  sO2  = (float*)(smem_raw + SP_BYTES + SO0_BYTES + SS1_BYTES); // [16]

    const int tid = threadIdx.x;
    const int b   = blockIdx.y;
    const int base_t = blockIdx.x * TILE;
    const float k = KF();

    // pair-table fill: 4 x LDG.128 per thread (2560 float4)
    #pragma unroll
    for (int it = 0; it < (WT_LEN * 5) / TPB; it++)
        sp4t[tid + it * TPB] = g_wtp4t[tid + it * TPB];

    // stage S1 window + O2 predecessors for this tile
    const int g0 = base_t >> 4;                      // first group (mult of 200)
    const int a0 = (g0 > 0) ? ((g0 - 1) & ~15) : 0;  // 16-aligned window start
    const int nS1 = g0 + NGRP - a0;                  // <= 216
    const int blkbase = a0 >> 4;
    if (tid < nS1) sS1[tid] = g_S1[b][a0 + tid];
    if (tid >= 624 && tid < 640) {                   // separate warp for O2
        int o2i = blkbase - 1 + (tid - 624);
        sO2[tid - 624] = (o2i >= 0) ? g_O2[b][o2i] : 0.0f;
    }
    __syncthreads();

    // O0 preamble: threads 0..199 each own one 16-group
    if (tid < NGRP) {
        const int gj = g0 + tid;
        float o1p = 0.0f;
        bool has_prev = (gj > 0);
        if (has_prev) {
            int m = gj - 1;
            int blk = m >> 4;
            float acc = 0.0f;
            for (int q = (blk << 4); q <= m; q++)
                acc = __fadd_rn(acc, sS1[q - a0]);
            o1p = blk ? __fadd_rn(acc, sO2[blk - blkbase]) : acc;
        }
        const float4* P4 = (const float4*)(pitch + b * L_DIM + base_t + (tid << 4));
        float4 v0 = P4[0], v1 = P4[1], v2 = P4[2], v3 = P4[3];
        const float vals[16] = {v0.x, v0.y, v0.z, v0.w, v1.x, v1.y, v1.z, v1.w,
                                v2.x, v2.y, v2.z, v2.w, v3.x, v3.y, v3.z, v3.w};
        float* dst = so0 + (tid << 4);
        float acc = 0.0f;
        #pragma unroll
        for (int e = 0; e < 16; e++) {
            acc = __fadd_rn(acc, __fmul_rn(k, vals[e]));
            dst[e] = has_prev ? __fadd_rn(acc, o1p) : acc;
        }
    }
    __syncthreads();

    #pragma unroll 1
    for (int s = 0; s < SAMP; s++) {
        const int m = tid + s * TPB;
        const int t = base_t + m;

        float v = so0[m];

        // index = cumsum - rn(k * pitch_row0[t])
        float index = __fsub_rn(v, __fmul_rn(k, pitch[t]));

        // exact trunc-remainder by 512 (bitwise == fmodf) + jnp.remainder fixup
        float q = truncf(__fmul_rn(index, 0.001953125f));
        float r = __fmaf_rn(-512.0f, q, index);
        if (r < 0.0f) r = __fadd_rn(r, 512.0f);
        if (__fsub_rn(512.0f, r) < 1e-5f) r = 0.0f;

        float lof   = floorf(r);
        float alpha = __fsub_rn(r, lof);
        int   ilo   = (int)lof;

        const int basei = b * L_DIM + t;
        const float2* ap = (const float2*)(att + (size_t)basei * N_WT);
        float2 a0v = ap[0], a1v = ap[1], a2v = ap[2], a3v = ap[3], a4v = ap[4];
        float aw[N_WT] = {a0v.x, a0v.y, a1v.x, a1v.y, a2v.x,
                          a2v.y, a3v.x, a3v.y, a4v.x, a4v.y};

        // 5 x LDS.128 from contiguous addresses; dot strict w-ascending
        const float4* tp = sp4t + ilo * 5;
        float acc2 = 0.0f;
        #pragma unroll
        for (int jj = 0; jj < 5; jj++) {
            float4 p = tp[jj];
            float wave0 = __fadd_rn(p.x, __fmul_rn(alpha, __fsub_rn(p.y, p.x)));
            acc2 = __fadd_rn(acc2, __fmul_rn(wave0, aw[2 * jj]));
            float wave1 = __fadd_rn(p.z, __fmul_rn(alpha, __fsub_rn(p.w, p.z)));
            acc2 = __fadd_rn(acc2, __fmul_rn(wave1, aw[2 * jj + 1]));
        }
        out[basei] = __fmul_rn(acc2, env[basei]);
    }
}

// ---------------------------------------------------------------------------
// d_in order: 0 pitch, 1 envelope, 2 attention, 3 wavetables, 4 fir_h
// ---------------------------------------------------------------------------
extern "C" void kernel_launch(void* const* d_in, const int* in_sizes, int n_in,
                              void* d_out, int out_size)
{
    const float* pitch = (const float*)d_in[0];
    const float* env   = (const float*)d_in[1];
    const float* att   = (const float*)d_in[2];
    const float* wtab  = (const float*)d_in[3];
    const float* firh  = (const float*)d_in[4];
    float* out = (float*)d_out;

    cudaFuncSetAttribute(k_main, cudaFuncAttributeMaxDynamicSharedMemorySize,
                         SMEM_MAIN);

    k_s1<<<dim3(S1_TILES, B_DIM), 512>>>(pitch);
    k_scan<<<B_DIM + 5, 1024>>>(wtab, firh);
    k_main<<<dim3(L_DIM / TILE, B_DIM), TPB, SMEM_MAIN>>>(pitch, env, att, out);
}

// round 16
// speedup vs baseline: 1.0180x; 1.0180x over previous
#include <cuda_runtime.h>
#include <cstdint>

// Problem constants
#define B_DIM   16
#define L_DIM   160000
#define N_WT    10
#define WT_LEN  512
#define FIR_TAPS 31
#define WT_TOT  (N_WT * WT_LEN)

// Blocked-scan parameters (XLA ReduceWindowRewriter, base_length = 16)
#define NS1 10000
#define NS2 625
#define NS3 40
#define NS4 3

// k_main tiling: 640 threads x 5 samples = 3200-sample tiles, 50 tiles/row
#define TPB   640
#define SAMP  5
#define TILE  (TPB * SAMP)          // 3200
#define NGRP  (TILE / 16)           // 200 16-groups per tile

// k_s1 tiling: 20 tiles/row, 500 S1 groups per tile (512-thread blocks)
#define S1_TILES 20
#define S1_GRP   500

// k_main dynamic smem: transposed pair table + finished cumsums
#define SP_BYTES   (WT_LEN * 5 * 16)   // 40960 (512 x 5 float4)
#define SO0_BYTES  (TILE * 4)          // 12800
#define SMEM_MAIN  (SP_BYTES + SO0_BYTES)   // 53760

__device__ __forceinline__ float KF() { return (float)(512.0 / 16000.0); }

// Scratch
__device__ float  g_S1[B_DIM][NS1];     // 16-block sums of increments
__device__ float  g_O1[B_DIM][NS1];     // composed inclusive scan at level 1
__device__ float4 g_wtp4t[WT_LEN * 5];  // transposed pairs [i][j]={lo2j,hi2j,lo2j+1,hi2j+1}

// ---------------------------------------------------------------------------
// k_s1: pure S1 — one 16-group per thread, 4x LDG.128, strict sequential rn
// adds in register order (verified bracketing).
// ---------------------------------------------------------------------------
__global__ void __launch_bounds__(512) k_s1(const float* __restrict__ pitch)
{
    const int tid = threadIdx.x;
    const int j = blockIdx.x * S1_GRP + tid;
    if (tid >= S1_GRP) return;
    const int b = blockIdx.y;
    const float k = KF();
    const float4* P4 = (const float4*)(pitch + b * L_DIM + (j << 4));
    float4 v0 = P4[0], v1 = P4[1], v2 = P4[2], v3 = P4[3];

    float acc = 0.0f;
    acc = __fadd_rn(acc, __fmul_rn(k, v0.x));
    acc = __fadd_rn(acc, __fmul_rn(k, v0.y));
    acc = __fadd_rn(acc, __fmul_rn(k, v0.z));
    acc = __fadd_rn(acc, __fmul_rn(k, v0.w));
    acc = __fadd_rn(acc, __fmul_rn(k, v1.x));
    acc = __fadd_rn(acc, __fmul_rn(k, v1.y));
    acc = __fadd_rn(acc, __fmul_rn(k, v1.z));
    acc = __fadd_rn(acc, __fmul_rn(k, v1.w));
    acc = __fadd_rn(acc, __fmul_rn(k, v2.x));
    acc = __fadd_rn(acc, __fmul_rn(k, v2.y));
    acc = __fadd_rn(acc, __fmul_rn(k, v2.z));
    acc = __fadd_rn(acc, __fmul_rn(k, v2.w));
    acc = __fadd_rn(acc, __fmul_rn(k, v3.x));
    acc = __fadd_rn(acc, __fmul_rn(k, v3.y));
    acc = __fadd_rn(acc, __fmul_rn(k, v3.z));
    acc = __fadd_rn(acc, __fmul_rn(k, v3.w));
    g_S1[b][j] = acc;
}

// ---------------------------------------------------------------------------
// k_scan: blocks 0..15: per-row S2 -> S3 -> S4 -> O4 -> O3 -> O2 -> O1
// (verified chain), O1 computed in-place over the padded buffer and written
// out coalesced.  Blocks 16..20: FIR rows (2jj, 2jj+1) + transposed pair
// writeout.  smem is a UNION of the two paths (47.8 KB < 48 KB).
// ---------------------------------------------------------------------------
__global__ void k_scan(const float* __restrict__ wtab,
                       const float* __restrict__ firh)
{
    __shared__ union {
        struct {
            float s1p[NS2 * 17];            // 42500 B (S1, then O1 in place)
            float sS2[NS2];                 // 2500 B
            float sS3[NS3];
            float sS4[NS4];
            float sO4[NS4];
            float sO3[NS3];
            float sO2[NS2];                 // 2500 B
        } sc;                               // 47844 B
        struct {
            float srow[2][WT_LEN];
            float sout[2][WT_LEN];
            float sh[FIR_TAPS];
        } fir;                              // ~8.3 KB
    } u;

    const int tid = threadIdx.x;

    if (blockIdx.x >= B_DIM) {                  // FIR pair block
        const int jj = blockIdx.x - B_DIM;      // 0..4 -> rows 2jj, 2jj+1
        if (tid < FIR_TAPS) u.fir.sh[tid] = firh[tid];
        if (tid < WT_LEN) {
            u.fir.srow[0][tid] = wtab[(2 * jj    ) * WT_LEN + tid];
            u.fir.srow[1][tid] = wtab[(2 * jj + 1) * WT_LEN + tid];
        }
        __syncthreads();
        if (tid < WT_LEN) {
            #pragma unroll
            for (int rr = 0; rr < 2; rr++) {
                float s = 0.0f;
                #pragma unroll
                for (int k = 0; k < FIR_TAPS; k++) {
                    int j = (tid + k - 15 + WT_LEN) & 511;
                    s = __fadd_rn(s, __fmul_rn(u.fir.srow[rr][j], u.fir.sh[k]));
                }
                u.fir.sout[rr][tid] = s;
            }
        }
        __syncthreads();
        if (tid < WT_LEN) {
            int ip1 = (tid + 1) & 511;
            float4 v;
            v.x = u.fir.sout[0][tid]; v.y = u.fir.sout[0][ip1];
            v.z = u.fir.sout[1][tid]; v.w = u.fir.sout[1][ip1];
            g_wtp4t[tid * 5 + jj] = v;
        }
        return;
    }

    const int b = blockIdx.x;

    // stage S1 into pad-17 layout (coalesced LDG)
    for (int i = tid; i < NS1; i += 1024)
        u.sc.s1p[(i >> 4) * 17 + (i & 15)] = g_S1[b][i];
    __syncthreads();

    if (tid < NS2) {                         // S2: strict 16-sums
        const float* row = u.sc.s1p + tid * 17;
        float acc = 0.0f;
        #pragma unroll
        for (int e = 0; e < 16; e++)
            acc = __fadd_rn(acc, row[e]);
        u.sc.sS2[tid] = acc;
    }
    __syncthreads();

    if (tid < NS3) {                         // S3 (625 padded to 640)
        float acc = 0.0f;
        for (int e = 0; e < 16; e++) {
            int idx = (tid << 4) + e;
            if (idx < NS2) acc = __fadd_rn(acc, u.sc.sS2[idx]);
        }
        u.sc.sS3[tid] = acc;
    }
    __syncthreads();

    if (tid < NS4) {                         // S4 (40 padded to 48)
        float acc = 0.0f;
        for (int e = 0; e < 16; e++) {
            int idx = (tid << 4) + e;
            if (idx < NS3) acc = __fadd_rn(acc, u.sc.sS3[idx]);
        }
        u.sc.sS4[tid] = acc;
    }
    __syncthreads();

    if (tid == 0) {                          // O4 sequential
        float acc = 0.0f;
        for (int m = 0; m < NS4; m++) {
            acc = __fadd_rn(acc, u.sc.sS4[m]);
            u.sc.sO4[m] = acc;
        }
    }
    __syncthreads();

    if (tid < NS3) {                         // O3
        int blk = tid >> 4;
        float acc = 0.0f;
        for (int m = (blk << 4); m <= tid; m++)
            acc = __fadd_rn(acc, u.sc.sS3[m]);
        u.sc.sO3[tid] = blk ? __fadd_rn(acc, u.sc.sO4[blk - 1]) : acc;
    }
    __syncthreads();

    if (tid < NS2) {                         // O2
        int blk = tid >> 4;
        float acc = 0.0f;
        for (int m = (blk << 4); m <= tid; m++)
            acc = __fadd_rn(acc, u.sc.sS2[m]);
        u.sc.sO2[tid] = blk ? __fadd_rn(acc, u.sc.sO3[blk - 1]) : acc;
    }
    __syncthreads();

    // O1 in place: thread j owns group j, running strict prefix
    if (tid < NS2) {
        float* row = u.sc.s1p + tid * 17;
        float prev = (tid > 0) ? u.sc.sO2[tid - 1] : 0.0f;
        float acc = 0.0f;
        #pragma unroll
        for (int e = 0; e < 16; e++) {
            acc = __fadd_rn(acc, row[e]);
            row[e] = (tid > 0) ? __fadd_rn(acc, prev) : acc;
        }
    }
    __syncthreads();

    // coalesced writeout
    for (int i = tid; i < NS1; i += 1024)
        g_O1[b][i] = u.sc.s1p[(i >> 4) * 17 + (i & 15)];
}

// ---------------------------------------------------------------------------
// k_main: EXACT R13 version (verified 43.5us, rel_err 1.379262e-7).
// O0 preamble (200 owner threads, verified 16-add chains composed with
// g_O1[gj-1]) + transposed pair table + per-sample loop.
// ---------------------------------------------------------------------------
__global__ void __launch_bounds__(TPB, 3) k_main(
        const float* __restrict__ pitch,
        const float* __restrict__ env,
        const float* __restrict__ att,
        float* __restrict__ out)
{
    extern __shared__ char smem_raw[];
    float4* sp4t = (float4*)smem_raw;                   // [512*5]
    float*  so0  = (float*)(smem_raw + SP_BYTES);       // [3200] finished cumsums

    const int tid = threadIdx.x;
    const int b   = blockIdx.y;
    const int base_t = blockIdx.x * TILE;
    const float k = KF();

    // pair-table fill: 4 x LDG.128 per thread (2560 float4)
    #pragma unroll
    for (int it = 0; it < (WT_LEN * 5) / TPB; it++)
        sp4t[tid + it * TPB] = g_wtp4t[tid + it * TPB];

    // O0 preamble: threads 0..199 each own one 16-group
    if (tid < NGRP) {
        const int gj = (base_t >> 4) + tid;             // global group id
        const float4* P4 = (const float4*)(pitch + b * L_DIM + base_t + (tid << 4));
        float4 v0 = P4[0], v1 = P4[1], v2 = P4[2], v3 = P4[3];
        const float vals[16] = {v0.x, v0.y, v0.z, v0.w, v1.x, v1.y, v1.z, v1.w,
                                v2.x, v2.y, v2.z, v2.w, v3.x, v3.y, v3.z, v3.w};
        const bool  has_prev = (gj > 0);
        const float o1p = has_prev ? g_O1[b][gj - 1] : 0.0f;
        float* dst = so0 + (tid << 4);
        float acc = 0.0f;
        #pragma unroll
        for (int e = 0; e < 16; e++) {
            acc = __fadd_rn(acc, __fmul_rn(k, vals[e]));
            dst[e] = has_prev ? __fadd_rn(acc, o1p) : acc;
        }
    }
    __syncthreads();

    #pragma unroll 1
    for (int s = 0; s < SAMP; s++) {
        const int m = tid + s * TPB;
        const int t = base_t + m;

        // finished cumsum (bitwise == verified chain)
        float v = so0[m];

        // index = cumsum - rn(k * pitch_row0[t])
        float index = __fsub_rn(v, __fmul_rn(k, pitch[t]));

        // exact trunc-remainder by 512 (bitwise == fmodf) + jnp.remainder fixup
        float q = truncf(__fmul_rn(index, 0.001953125f));
        float r = __fmaf_rn(-512.0f, q, index);
        if (r < 0.0f) r = __fadd_rn(r, 512.0f);
        if (__fsub_rn(512.0f, r) < 1e-5f) r = 0.0f;

        float lof   = floorf(r);
        float alpha = __fsub_rn(r, lof);
        int   ilo   = (int)lof;

        const int basei = b * L_DIM + t;
        const float2* ap = (const float2*)(att + (size_t)basei * N_WT);
        float2 a0 = ap[0], a1 = ap[1], a2 = ap[2], a3 = ap[3], a4 = ap[4];
        float aw[N_WT] = {a0.x, a0.y, a1.x, a1.y, a2.x,
                          a2.y, a3.x, a3.y, a4.x, a4.y};

        // 5 x LDS.128 from contiguous addresses; dot strict w-ascending
        const float4* tp = sp4t + ilo * 5;
        float acc2 = 0.0f;
        #pragma unroll
        for (int jj = 0; jj < 5; jj++) {
            float4 p = tp[jj];
            float wave0 = __fadd_rn(p.x, __fmul_rn(alpha, __fsub_rn(p.y, p.x)));
            acc2 = __fadd_rn(acc2, __fmul_rn(wave0, aw[2 * jj]));
            float wave1 = __fadd_rn(p.z, __fmul_rn(alpha, __fsub_rn(p.w, p.z)));
            acc2 = __fadd_rn(acc2, __fmul_rn(wave1, aw[2 * jj + 1]));
        }
        out[basei] = __fmul_rn(acc2, env[basei]);
    }
}

// ---------------------------------------------------------------------------
// d_in order: 0 pitch, 1 envelope, 2 attention, 3 wavetables, 4 fir_h
// ---------------------------------------------------------------------------
extern "C" void kernel_launch(void* const* d_in, const int* in_sizes, int n_in,
                              void* d_out, int out_size)
{
    const float* pitch = (const float*)d_in[0];
    const float* env   = (const float*)d_in[1];
    const float* att   = (const float*)d_in[2];
    const float* wtab  = (const float*)d_in[3];
    const float* firh  = (const float*)d_in[4];
    float* out = (float*)d_out;

    cudaFuncSetAttribute(k_main, cudaFuncAttributeMaxDynamicSharedMemorySize,
                         SMEM_MAIN);

    k_s1<<<dim3(S1_TILES, B_DIM), 512>>>(pitch);
    k_scan<<<B_DIM + 5, 1024>>>(wtab, firh);
    k_main<<<dim3(L_DIM / TILE, B_DIM), TPB, SMEM_MAIN>>>(pitch, env, att, out);
}